// round 6
// baseline (speedup 1.0000x reference)
#include <cuda_runtime.h>
#include <math.h>

#define NNODES 30000
#define DIM    128
#define TLINKS 3000
#define KNEG   75
#define GAMMA  1.0f
#define MAXSQ  50.0f
// float(1.0 + 1e-7) == 0x3F800001 (1 ulp above 1.0f) — matches XLA's f32 cast
#define THETA0 (1.0f + 1e-7f)

// ---- device scratch (no allocation allowed) ----
__device__ double       g_part[TLINKS];   // per-link contribution
__device__ unsigned int g_ticket = 0;     // wraps mod TLINKS each replay

// ---------------------------------------------------------------------------
__device__ __forceinline__ float sqdist_from_mdot(float mdot, float cval, float Kv) {
    float th = fmaxf(-mdot * cval, THETA0);
    float a  = acoshf(th);
    return fminf(Kv * a * a, MAXSQ);
}

// full 128-dim Minkowski sqdist, one thread (fallback path only)
__device__ __forceinline__ float sqdist_full(const float* __restrict__ q,
                                             const float* __restrict__ row,
                                             float cval, float Kv) {
    float md = 0.f;
#pragma unroll
    for (int d = 0; d < DIM; d++) {
        float p = q[d] * row[d];
        md += (d == 0) ? -p : p;
    }
    return sqdist_from_mdot(md, cval, Kv);
}

// ---------------------------------------------------------------------------
// Exact fallback (essentially never taken; kept for correctness): block-wide
// MSB-first radix select of the 75th smallest sqdist tau over all 30000
// candidates, then sum relu(D - v) over values < tau plus ties at tau.
// Result valid on tid 0.
__device__ double fallback_query(const float* __restrict__ q,
                                 const float* __restrict__ emb,
                                 float cval, float Kv, float D,
                                 unsigned int* hist, unsigned int* s_prefix,
                                 int* s_k, double* ssum, int* scm) {
    const int tid = threadIdx.x;
    if (tid == 0) { *s_prefix = 0u; *s_k = KNEG; }
    __syncthreads();

    for (int pass = 0; pass < 4; pass++) {
        const int shift = 24 - 8 * pass;
        const unsigned int pmask  = (pass == 0) ? 0u : (0xFFFFFFFFu << (shift + 8));
        const unsigned int prefix = *s_prefix;
        hist[tid] = 0u;
        __syncthreads();
        for (int j = tid; j < NNODES; j += 256) {
            float v = sqdist_full(q, emb + (size_t)j * DIM, cval, Kv);
            unsigned int b = __float_as_uint(v);
            if ((b & pmask) == prefix)
                atomicAdd(&hist[(b >> shift) & 0xFFu], 1u);
        }
        __syncthreads();
        if (tid == 0) {
            int k = *s_k;
            unsigned int acc = 0;
            int digit = 0;
            for (; digit < 255; digit++) {
                if (acc + hist[digit] >= (unsigned)k) break;
                acc += hist[digit];
            }
            *s_k      = k - (int)acc;
            *s_prefix = prefix | ((unsigned)digit << shift);
        }
        __syncthreads();
    }

    const unsigned int tau_bits = *s_prefix;
    const float        tau      = __uint_as_float(tau_bits);

    int    m_local = 0;
    double sum_local = 0.0;
    for (int j = tid; j < NNODES; j += 256) {
        float v = sqdist_full(q, emb + (size_t)j * DIM, cval, Kv);
        if (__float_as_uint(v) < tau_bits) {
            m_local++;
            sum_local += (double)fmaxf(D - v, 0.f);
        }
    }
    ssum[tid] = sum_local;
    scm[tid]  = m_local;
    __syncthreads();
    for (int o = 128; o > 0; o >>= 1) {
        if (tid < o) { ssum[tid] += ssum[tid + o]; scm[tid] += scm[tid + o]; }
        __syncthreads();
    }
    double res = 0.0;
    if (tid == 0) {
        int m = scm[0];
        res = ssum[0] + (double)(KNEG - m) * (double)fmaxf(D - tau, 0.f);
    }
    __syncthreads();
    return res;
}

// ---------------------------------------------------------------------------
// Fused kernel: one block (256 threads) per link; last-arriving block reduces.
//  - per-block inline int64/int32 links detection (register result)
//  - both query rows staged via float4 (lanes 0-31 / 32-63)
//  - candidate scan: 8-lane sub-groups each own one row (16 dims/lane),
//    both queries per pass; count rows with theta clipped
//    (mdot >= -THETA0/c  <=>  sqdist == S0 == global minimum).
//  - count >= 75  =>  top-75 all exactly S0  =>  contribution is
//    75 * relu(D - S0); else exact radix-select fallback.
//  - per-link double partial -> g_part[t]; wrap-around ticket elects the
//    last block, which does a fixed-order fp64 reduction and writes out.
__global__ void __launch_bounds__(256) fused_kernel(const float* __restrict__ emb,
                                                    const float* __restrict__ cptr,
                                                    const void*  __restrict__ links,
                                                    float*       __restrict__ out) {
    __shared__ float        q[2][DIM];
    __shared__ float        sD;
    __shared__ int          sc0, sc1;
    __shared__ int          s_last;
    __shared__ unsigned int hist[256];
    __shared__ unsigned int s_prefix;
    __shared__ int          s_k;
    __shared__ double       ssum[256];
    __shared__ int          scm[256];

    const int t    = blockIdx.x;
    const int tid  = threadIdx.x;
    const int w    = tid >> 5;
    const int lane = tid & 31;
    const int sub  = lane & 7;          // 8-lane sub-group position

    const float cval = cptr[0];
    const float Kv   = 1.0f / cval;

    // ---- per-block dtype detection (int64 values < 30000 -> odd words 0) ----
    const int* links32 = (const int*)links;
    int bad = 0;
    for (int i = tid; i < TLINKS; i += 256)
        if (links32[2 * i + 1] != 0) bad = 1;
    const int is64 = __syncthreads_or(bad) ? 0 : 1;

    const long long L = is64 ? ((const long long*)links)[2 * t]
                             : (long long)links32[2 * t];
    const long long R = is64 ? ((const long long*)links)[2 * t + 1]
                             : (long long)links32[2 * t + 1];

    // ---- stage query rows (float4, one LDG.128 per lane) ----
    if (tid < 32)       ((float4*)q[0])[tid]      = ((const float4*)(emb + (size_t)L * DIM))[tid];
    else if (tid < 64)  ((float4*)q[1])[tid - 32] = ((const float4*)(emb + (size_t)R * DIM))[tid - 32];
    if (tid == 0) { sc0 = 0; sc1 = 0; }
    __syncthreads();

    // per-lane 16-dim register slices of both queries, dim-0 sign folded in
    float4 a0[4], a1[4];
#pragma unroll
    for (int i = 0; i < 4; i++) {
        a0[i] = *(const float4*)&q[0][sub * 16 + i * 4];
        a1[i] = *(const float4*)&q[1][sub * 16 + i * 4];
    }
    if (sub == 0) { a0[0].x = -a0[0].x; a1[0].x = -a1[0].x; }

    // D = sqdist(left,right) + GAMMA  (sign-folded a0 vs RAW q1)
    if (w == 0) {
        float s = 0.f;
#pragma unroll
        for (int i = 0; i < 4; i++) {
            float4 b = *(const float4*)&q[1][sub * 16 + i * 4];
            s += a0[i].x * b.x + a0[i].y * b.y + a0[i].z * b.z + a0[i].w * b.w;
        }
        s += __shfl_xor_sync(0xffffffffu, s, 1);
        s += __shfl_xor_sync(0xffffffffu, s, 2);
        s += __shfl_xor_sync(0xffffffffu, s, 4);
        if (tid == 0) sD = sqdist_from_mdot(s, cval, Kv) + GAMMA;
    }
    __syncthreads();
    const float D = sD;

    float acz = acoshf(THETA0);
    const float S0  = fminf(Kv * acz * acz, MAXSQ);
    const float thr = -(THETA0 * Kv);    // mdot >= thr  <=>  theta clips to 1+EPS

    int c0 = 0, c1 = 0;
    int base = 0;
    while (base < NNODES && (c0 < KNEG || c1 < KNEG)) {
        const int rbase = base + (w << 5) + (lane >> 3);
        int l0 = 0, l1 = 0;
#pragma unroll 2
        for (int g = 0; g < 8; g++) {
            int row = rbase + g * 4;
            float s0 = -1e30f, s1 = -1e30f;
            if (row < NNODES) {
                const float4* p = (const float4*)(emb + (size_t)row * DIM + sub * 16);
                s0 = 0.f; s1 = 0.f;
#pragma unroll
                for (int i = 0; i < 4; i++) {
                    float4 y = p[i];
                    s0 += a0[i].x * y.x + a0[i].y * y.y + a0[i].z * y.z + a0[i].w * y.w;
                    s1 += a1[i].x * y.x + a1[i].y * y.y + a1[i].z * y.z + a1[i].w * y.w;
                }
            }
            // 3-step butterfly within the 8-lane sub-group (both queries)
            s0 += __shfl_xor_sync(0xffffffffu, s0, 1);
            s1 += __shfl_xor_sync(0xffffffffu, s1, 1);
            s0 += __shfl_xor_sync(0xffffffffu, s0, 2);
            s1 += __shfl_xor_sync(0xffffffffu, s1, 2);
            s0 += __shfl_xor_sync(0xffffffffu, s0, 4);
            s1 += __shfl_xor_sync(0xffffffffu, s1, 4);
            // s0/s1 replicated over the sub-group's 8 lanes: one count per row
            l0 += (s0 >= thr);
            l1 += (s1 >= thr);
        }
        // lanes 0-7 hold subgroup0's count, 8-15 subgroup1's, ...:
        // xor8 + xor16 -> exact warp count on every lane (no division).
        l0 += __shfl_xor_sync(0xffffffffu, l0, 8);
        l1 += __shfl_xor_sync(0xffffffffu, l1, 8);
        l0 += __shfl_xor_sync(0xffffffffu, l0, 16);
        l1 += __shfl_xor_sync(0xffffffffu, l1, 16);
        if (lane == 0) { atomicAdd(&sc0, l0); atomicAdd(&sc1, l1); }
        __syncthreads();
        c0 = sc0; c1 = sc1;
        __syncthreads();
        base += 256;
    }

    double contrib = 0.0;
    if (c0 >= KNEG) {
        if (tid == 0) contrib += (double)KNEG * (double)fmaxf(D - S0, 0.f);
    } else {
        double r = fallback_query(q[0], emb, cval, Kv, D, hist, &s_prefix, &s_k, ssum, scm);
        if (tid == 0) contrib += r;
    }
    if (c1 >= KNEG) {
        if (tid == 0) contrib += (double)KNEG * (double)fmaxf(D - S0, 0.f);
    } else {
        double r = fallback_query(q[1], emb, cval, Kv, D, hist, &s_prefix, &s_k, ssum, scm);
        if (tid == 0) contrib += r;
    }

    // ---- publish partial, elect last block via wrap-around ticket ----
    if (tid == 0) {
        g_part[t] = contrib;
        __threadfence();
        unsigned int old = atomicInc(&g_ticket, TLINKS - 1);  // wraps to 0 at 2999
        s_last = (old == TLINKS - 1);
    }
    __syncthreads();

    if (s_last) {
        __threadfence();
        const volatile double* vp = g_part;
        double s = 0.0;
        for (int i = tid; i < TLINKS; i += 256) s += vp[i];
        ssum[tid] = s;
        __syncthreads();
        for (int o = 128; o > 0; o >>= 1) {
            if (tid < o) ssum[tid] += ssum[tid + o];
            __syncthreads();
        }
        if (tid == 0)
            out[0] = (float)(ssum[0] / (2.0 * (double)KNEG * (double)TLINKS));
    }
}

// ---------------------------------------------------------------------------
extern "C" void kernel_launch(void* const* d_in, const int* in_sizes, int n_in,
                              void* d_out, int out_size) {
    const float* emb   = nullptr;
    const float* c     = nullptr;
    const void*  links = nullptr;
    for (int i = 0; i < n_in; i++) {
        if (in_sizes[i] == 1)               c     = (const float*)d_in[i];
        else if (in_sizes[i] == 2 * TLINKS) links = d_in[i];
        else                                emb   = (const float*)d_in[i];
    }

    fused_kernel<<<TLINKS, 256>>>(emb, c, links, (float*)d_out);
}

// round 8
// speedup vs baseline: 1.6480x; 1.6480x over previous
#include <cuda_runtime.h>
#include <math.h>

#define NNODES 30000
#define DIM    128
#define TLINKS 3000
#define KNEG   75
#define GAMMA  1.0f
#define MAXSQ  50.0f
// float(1.0 + 1e-7) == 0x3F800001 (1 ulp above 1.0f) — matches XLA's f32 cast
#define THETA0 (1.0f + 1e-7f)

// ---- device scratch (no allocation allowed) ----
__device__ double g_part[TLINKS];     // per-link fast-path contribution
__device__ float  g_D[TLINKS];        // per-link D = sqdist(l,r)+GAMMA
__device__ int    g_flags[2*TLINKS];  // per-query fallback flag (0/1)
__device__ double g_fb[2*TLINKS];     // per-query fallback contribution
__device__ int    g_is64;             // links dtype: 1 = int64, 0 = int32

// ---------------------------------------------------------------------------
__device__ __forceinline__ float sqdist_from_mdot(float mdot, float cval, float Kv) {
    float th = fmaxf(-mdot * cval, THETA0);
    float a  = acoshf(th);
    return fminf(Kv * a * a, MAXSQ);
}

// full 128-dim Minkowski sqdist, one thread (fallback path only)
__device__ __forceinline__ float sqdist_full(const float* __restrict__ q,
                                             const float* __restrict__ row,
                                             float cval, float Kv) {
    float md = 0.f;
#pragma unroll
    for (int d = 0; d < DIM; d++) {
        float p = q[d] * row[d];
        md += (d == 0) ? -p : p;
    }
    return sqdist_from_mdot(md, cval, Kv);
}

__device__ __forceinline__ long long get_link(const void* links, int pos, int is64) {
    return is64 ? ((const long long*)links)[pos]
                : (long long)((const int*)links)[pos];
}

// ---------------------------------------------------------------------------
// setup: detect int64-vs-int32 links (int64 values < 30000 -> odd words 0).
__global__ void setup_kernel(const int* __restrict__ links32) {
    int bad = 0;
    for (int i = threadIdx.x; i < TLINKS; i += blockDim.x)
        if (links32[2 * i + 1] != 0) bad = 1;
    int any = __syncthreads_or(bad);
    if (threadIdx.x == 0) g_is64 = any ? 0 : 1;
}

// ---------------------------------------------------------------------------
// HOT kernel: one block (256 threads) per link. Fast path only — no fp64
// radix machinery in here, so regs stay low and 3 blocks/SM are resident.
//  - candidate scan: 8-lane sub-groups each own one row (16 dims/lane),
//    both queries per pass; count rows with theta clipped
//    (mdot >= -THETA0/c  <=>  sqdist == S0 == the global minimum value).
//  - count >= 75  =>  the 75 smallest sqdists are all exactly S0  =>
//    contribution = 75 * relu(D - S0). Else flag for the exact fallback.
__global__ void __launch_bounds__(256, 3) hot_kernel(const float* __restrict__ emb,
                                                     const float* __restrict__ cptr,
                                                     const void*  __restrict__ links) {
    __shared__ float q[2][DIM];
    __shared__ float sD;
    __shared__ int   sc0, sc1;

    const int t    = blockIdx.x;
    const int tid  = threadIdx.x;
    const int w    = tid >> 5;
    const int lane = tid & 31;
    const int sub  = lane & 7;          // 8-lane sub-group position

    const float cval = cptr[0];
    const float Kv   = 1.0f / cval;
    const int   is64 = g_is64;

    const long long L = get_link(links, 2 * t,     is64);
    const long long R = get_link(links, 2 * t + 1, is64);

    // stage query rows (float4, one LDG.128 per lane)
    if (tid < 32)       ((float4*)q[0])[tid]      = ((const float4*)(emb + (size_t)L * DIM))[tid];
    else if (tid < 64)  ((float4*)q[1])[tid - 32] = ((const float4*)(emb + (size_t)R * DIM))[tid - 32];
    if (tid == 0) { sc0 = 0; sc1 = 0; }
    __syncthreads();

    // per-lane 16-dim register slices of both queries, dim-0 sign folded in
    float4 a0[4], a1[4];
#pragma unroll
    for (int i = 0; i < 4; i++) {
        a0[i] = *(const float4*)&q[0][sub * 16 + i * 4];
        a1[i] = *(const float4*)&q[1][sub * 16 + i * 4];
    }
    if (sub == 0) { a0[0].x = -a0[0].x; a1[0].x = -a1[0].x; }

    // D = sqdist(left,right) + GAMMA  (sign-folded a0 vs RAW q1)
    if (w == 0) {
        float s = 0.f;
#pragma unroll
        for (int i = 0; i < 4; i++) {
            float4 b = *(const float4*)&q[1][sub * 16 + i * 4];
            s += a0[i].x * b.x + a0[i].y * b.y + a0[i].z * b.z + a0[i].w * b.w;
        }
        s += __shfl_xor_sync(0xffffffffu, s, 1);
        s += __shfl_xor_sync(0xffffffffu, s, 2);
        s += __shfl_xor_sync(0xffffffffu, s, 4);
        if (tid == 0) sD = sqdist_from_mdot(s, cval, Kv) + GAMMA;
    }
    __syncthreads();
    const float D = sD;

    float acz = acoshf(THETA0);
    const float S0  = fminf(Kv * acz * acz, MAXSQ);
    const float thr = -(THETA0 * Kv);    // mdot >= thr  <=>  theta clips to 1+EPS

    int c0 = 0, c1 = 0;
    int base = 0;
    while (base < NNODES && (c0 < KNEG || c1 < KNEG)) {
        const int rbase = base + (w << 5) + (lane >> 3);
        int l0 = 0, l1 = 0;
#pragma unroll 2
        for (int g = 0; g < 8; g++) {
            int row = rbase + g * 4;
            float s0 = -1e30f, s1 = -1e30f;
            if (row < NNODES) {
                const float4* p = (const float4*)(emb + (size_t)row * DIM + sub * 16);
                s0 = 0.f; s1 = 0.f;
#pragma unroll
                for (int i = 0; i < 4; i++) {
                    float4 y = p[i];
                    s0 += a0[i].x * y.x + a0[i].y * y.y + a0[i].z * y.z + a0[i].w * y.w;
                    s1 += a1[i].x * y.x + a1[i].y * y.y + a1[i].z * y.z + a1[i].w * y.w;
                }
            }
            // 3-step butterfly within the 8-lane sub-group (both queries)
            s0 += __shfl_xor_sync(0xffffffffu, s0, 1);
            s1 += __shfl_xor_sync(0xffffffffu, s1, 1);
            s0 += __shfl_xor_sync(0xffffffffu, s0, 2);
            s1 += __shfl_xor_sync(0xffffffffu, s1, 2);
            s0 += __shfl_xor_sync(0xffffffffu, s0, 4);
            s1 += __shfl_xor_sync(0xffffffffu, s1, 4);
            // s0/s1 replicated over the sub-group's 8 lanes: one count per row
            l0 += (s0 >= thr);
            l1 += (s1 >= thr);
        }
        // lanes 0-7 hold subgroup0's count, 8-15 subgroup1's, ...:
        // xor8 + xor16 -> exact warp count on every lane (no division).
        l0 += __shfl_xor_sync(0xffffffffu, l0, 8);
        l1 += __shfl_xor_sync(0xffffffffu, l1, 8);
        l0 += __shfl_xor_sync(0xffffffffu, l0, 16);
        l1 += __shfl_xor_sync(0xffffffffu, l1, 16);
        if (lane == 0) { atomicAdd(&sc0, l0); atomicAdd(&sc1, l1); }
        __syncthreads();
        c0 = sc0; c1 = sc1;
        __syncthreads();
        base += 256;
    }

    if (tid == 0) {
        double fast = (double)KNEG * (double)fmaxf(D - S0, 0.f);
        double contrib = 0.0;
        if (c0 >= KNEG) contrib += fast;
        if (c1 >= KNEG) contrib += fast;
        g_part[t]           = contrib;
        g_D[t]              = D;
        g_flags[t]          = (c0 < KNEG);
        g_flags[TLINKS + t] = (c1 < KNEG);
    }
}

// ---------------------------------------------------------------------------
// Exact fallback (essentially never runs; early-exits on flag): block-wide
// MSB-first radix select of the 75th smallest sqdist tau over all 30000
// candidates, then sum relu(D - v) over values < tau plus ties at tau.
__global__ void __launch_bounds__(256) fallback_kernel(const float* __restrict__ emb,
                                                       const float* __restrict__ cptr,
                                                       const void*  __restrict__ links) {
    const int s   = blockIdx.x;
    const int tid = threadIdx.x;

    if (g_flags[s] == 0) {                  // uniform over block
        if (tid == 0) g_fb[s] = 0.0;
        return;
    }

    const int t    = s % TLINKS;
    const int side = s / TLINKS;            // 0 = left query, 1 = right query

    __shared__ float        q[DIM];
    __shared__ unsigned int hist[256];
    __shared__ unsigned int s_prefix;
    __shared__ int          s_k;
    __shared__ double       ssum[256];
    __shared__ int          scm[256];

    const float cval = cptr[0];
    const float Kv   = 1.0f / cval;
    const long long node = get_link(links, 2 * t + side, g_is64);

    if (tid < DIM) q[tid] = emb[(size_t)node * DIM + tid];
    if (tid == 0) { s_prefix = 0u; s_k = KNEG; }
    __syncthreads();

    const float D = g_D[t];

    for (int pass = 0; pass < 4; pass++) {
        const int shift = 24 - 8 * pass;
        const unsigned int pmask  = (pass == 0) ? 0u : (0xFFFFFFFFu << (shift + 8));
        const unsigned int prefix = s_prefix;
        hist[tid] = 0u;
        __syncthreads();
        for (int j = tid; j < NNODES; j += 256) {
            float v = sqdist_full(q, emb + (size_t)j * DIM, cval, Kv);
            unsigned int b = __float_as_uint(v);
            if ((b & pmask) == prefix)
                atomicAdd(&hist[(b >> shift) & 0xFFu], 1u);
        }
        __syncthreads();
        if (tid == 0) {
            int k = s_k;
            unsigned int acc = 0;
            int digit = 0;
            for (; digit < 255; digit++) {
                if (acc + hist[digit] >= (unsigned)k) break;
                acc += hist[digit];
            }
            s_k      = k - (int)acc;
            s_prefix = prefix | ((unsigned)digit << shift);
        }
        __syncthreads();
    }

    const unsigned int tau_bits = s_prefix;
    const float        tau      = __uint_as_float(tau_bits);

    int    m_local = 0;
    double sum_local = 0.0;
    for (int j = tid; j < NNODES; j += 256) {
        float v = sqdist_full(q, emb + (size_t)j * DIM, cval, Kv);
        if (__float_as_uint(v) < tau_bits) {
            m_local++;
            sum_local += (double)fmaxf(D - v, 0.f);
        }
    }
    ssum[tid] = sum_local;
    scm[tid]  = m_local;
    __syncthreads();
    for (int o = 128; o > 0; o >>= 1) {
        if (tid < o) { ssum[tid] += ssum[tid + o]; scm[tid] += scm[tid + o]; }
        __syncthreads();
    }
    if (tid == 0) {
        int m = scm[0];
        g_fb[s] = ssum[0] + (double)(KNEG - m) * (double)fmaxf(D - tau, 0.f);
    }
}

// ---------------------------------------------------------------------------
// finish: fixed-order fp64 reduction over 3000 + 6000 partials, 1024 threads.
__global__ void __launch_bounds__(1024) finish_kernel(float* __restrict__ out) {
    __shared__ double sh[1024];
    const int tid = threadIdx.x;
    double s = 0.0;
    for (int i = tid; i < TLINKS;     i += 1024) s += g_part[i];
    for (int i = tid; i < 2 * TLINKS; i += 1024) s += g_fb[i];
    sh[tid] = s;
    __syncthreads();
    for (int o = 512; o > 0; o >>= 1) {
        if (tid < o) sh[tid] += sh[tid + o];
        __syncthreads();
    }
    if (tid == 0)
        out[0] = (float)(sh[0] / (2.0 * (double)KNEG * (double)TLINKS));
}

// ---------------------------------------------------------------------------
extern "C" void kernel_launch(void* const* d_in, const int* in_sizes, int n_in,
                              void* d_out, int out_size) {
    const float* emb   = nullptr;
    const float* c     = nullptr;
    const void*  links = nullptr;
    for (int i = 0; i < n_in; i++) {
        if (in_sizes[i] == 1)               c     = (const float*)d_in[i];
        else if (in_sizes[i] == 2 * TLINKS) links = d_in[i];
        else                                emb   = (const float*)d_in[i];
    }

    setup_kernel   <<<1, 256>>>((const int*)links);
    hot_kernel     <<<TLINKS, 256>>>(emb, c, links);
    fallback_kernel<<<2 * TLINKS, 256>>>(emb, c, links);
    finish_kernel  <<<1, 1024>>>((float*)d_out);
}

// round 9
// speedup vs baseline: 1.8345x; 1.1132x over previous
#include <cuda_runtime.h>
#include <math.h>

#define NNODES 30000
#define DIM    128
#define TLINKS 3000
#define KNEG   75
#define GAMMA  1.0f
#define MAXSQ  50.0f
// float(1.0 + 1e-7) == 0x3F800001 (1 ulp above 1.0f) — matches XLA's f32 cast
#define THETA0 (1.0f + 1e-7f)

// ---- device scratch (no allocation allowed) ----
__device__ double       g_part[TLINKS];     // per-link fast-path contribution
__device__ float        g_D[TLINKS];        // per-link D = sqdist(l,r)+GAMMA
__device__ int          g_flags[2*TLINKS];  // per-query fallback flag (0/1)
__device__ double       g_fb[2*TLINKS];     // per-query fallback contribution
__device__ int          g_is64;             // links dtype: 1 = int64, 0 = int32
__device__ unsigned int g_ticket = 0;       // wraps mod 2*TLINKS each replay

// ---------------------------------------------------------------------------
__device__ __forceinline__ float sqdist_from_mdot(float mdot, float cval, float Kv) {
    float th = fmaxf(-mdot * cval, THETA0);
    float a  = acoshf(th);
    return fminf(Kv * a * a, MAXSQ);
}

// full 128-dim Minkowski sqdist, one thread (fallback path only)
__device__ __forceinline__ float sqdist_full(const float* __restrict__ q,
                                             const float* __restrict__ row,
                                             float cval, float Kv) {
    float md = 0.f;
#pragma unroll
    for (int d = 0; d < DIM; d++) {
        float p = q[d] * row[d];
        md += (d == 0) ? -p : p;
    }
    return sqdist_from_mdot(md, cval, Kv);
}

__device__ __forceinline__ long long get_link(const void* links, int pos, int is64) {
    return is64 ? ((const long long*)links)[pos]
                : (long long)((const int*)links)[pos];
}

// ---------------------------------------------------------------------------
// setup: detect int64-vs-int32 links (int64 values < 30000 -> odd words 0).
__global__ void setup_kernel(const int* __restrict__ links32) {
    int bad = 0;
    for (int i = threadIdx.x; i < TLINKS; i += blockDim.x)
        if (links32[2 * i + 1] != 0) bad = 1;
    int any = __syncthreads_or(bad);
    if (threadIdx.x == 0) g_is64 = any ? 0 : 1;
}

// ---------------------------------------------------------------------------
// HOT kernel: one block (256 threads) per link. Fast path only; low regs,
// 3 blocks/SM. COALESCED mapping: lane `sub` of each 8-lane sub-group owns
// float4s j = i*8+sub of its row, so for fixed i the sub-group reads one
// contiguous 128-B line (4 lines per warp LDG.128 — minimum possible).
//  - count rows with theta clipped (mdot >= -THETA0/c <=> sqdist == S0).
//  - count >= 75  =>  top-75 all exactly S0  =>  75 * relu(D - S0).
__global__ void __launch_bounds__(256, 3) hot_kernel(const float* __restrict__ emb,
                                                     const float* __restrict__ cptr,
                                                     const void*  __restrict__ links) {
    __shared__ float q[2][DIM];
    __shared__ float sD;
    __shared__ int   sc0, sc1;

    const int t    = blockIdx.x;
    const int tid  = threadIdx.x;
    const int w    = tid >> 5;
    const int lane = tid & 31;
    const int sub  = lane & 7;          // 8-lane sub-group position

    const float cval = cptr[0];
    const float Kv   = 1.0f / cval;
    const int   is64 = g_is64;

    const long long L = get_link(links, 2 * t,     is64);
    const long long R = get_link(links, 2 * t + 1, is64);

    // stage query rows (float4, one LDG.128 per lane)
    if (tid < 32)       ((float4*)q[0])[tid]      = ((const float4*)(emb + (size_t)L * DIM))[tid];
    else if (tid < 64)  ((float4*)q[1])[tid - 32] = ((const float4*)(emb + (size_t)R * DIM))[tid - 32];
    if (tid == 0) { sc0 = 0; sc1 = 0; }
    __syncthreads();

    // per-lane register slices, mapping j = i*8 + sub (dim 0 is i=0,sub=0,.x)
    float4 a0[4], a1[4];
#pragma unroll
    for (int i = 0; i < 4; i++) {
        a0[i] = ((const float4*)q[0])[i * 8 + sub];
        a1[i] = ((const float4*)q[1])[i * 8 + sub];
    }
    if (sub == 0) { a0[0].x = -a0[0].x; a1[0].x = -a1[0].x; }

    // D = sqdist(left,right) + GAMMA  (sign-folded a0 vs RAW q1)
    if (w == 0) {
        float s = 0.f;
#pragma unroll
        for (int i = 0; i < 4; i++) {
            float4 b = ((const float4*)q[1])[i * 8 + sub];
            s += a0[i].x * b.x + a0[i].y * b.y + a0[i].z * b.z + a0[i].w * b.w;
        }
        s += __shfl_xor_sync(0xffffffffu, s, 1);
        s += __shfl_xor_sync(0xffffffffu, s, 2);
        s += __shfl_xor_sync(0xffffffffu, s, 4);
        if (tid == 0) sD = sqdist_from_mdot(s, cval, Kv) + GAMMA;
    }
    __syncthreads();
    const float D = sD;

    float acz = acoshf(THETA0);
    const float S0  = fminf(Kv * acz * acz, MAXSQ);
    const float thr = -(THETA0 * Kv);    // mdot >= thr  <=>  theta clips to 1+EPS

    int c0 = 0, c1 = 0;
    int base = 0;
    while (base < NNODES && (c0 < KNEG || c1 < KNEG)) {
        const int rbase = base + (w << 5) + (lane >> 3);
        int l0 = 0, l1 = 0;
#pragma unroll 2
        for (int g = 0; g < 8; g++) {
            int row = rbase + g * 4;
            float s0 = -1e30f, s1 = -1e30f;
            if (row < NNODES) {
                const float4* p = (const float4*)(emb + (size_t)row * DIM);
                s0 = 0.f; s1 = 0.f;
#pragma unroll
                for (int i = 0; i < 4; i++) {
                    float4 y = p[i * 8 + sub];       // coalesced: 128-B line per sub-group
                    s0 += a0[i].x * y.x + a0[i].y * y.y + a0[i].z * y.z + a0[i].w * y.w;
                    s1 += a1[i].x * y.x + a1[i].y * y.y + a1[i].z * y.z + a1[i].w * y.w;
                }
            }
            // 3-step butterfly within the 8-lane sub-group (both queries)
            s0 += __shfl_xor_sync(0xffffffffu, s0, 1);
            s1 += __shfl_xor_sync(0xffffffffu, s1, 1);
            s0 += __shfl_xor_sync(0xffffffffu, s0, 2);
            s1 += __shfl_xor_sync(0xffffffffu, s1, 2);
            s0 += __shfl_xor_sync(0xffffffffu, s0, 4);
            s1 += __shfl_xor_sync(0xffffffffu, s1, 4);
            // s0/s1 replicated over the sub-group's 8 lanes: one count per row
            l0 += (s0 >= thr);
            l1 += (s1 >= thr);
        }
        // lanes 0-7 hold subgroup0's count, 8-15 subgroup1's, ...:
        // xor8 + xor16 -> exact warp count on every lane (no division).
        l0 += __shfl_xor_sync(0xffffffffu, l0, 8);
        l1 += __shfl_xor_sync(0xffffffffu, l1, 8);
        l0 += __shfl_xor_sync(0xffffffffu, l0, 16);
        l1 += __shfl_xor_sync(0xffffffffu, l1, 16);
        if (lane == 0) { atomicAdd(&sc0, l0); atomicAdd(&sc1, l1); }
        __syncthreads();
        c0 = sc0; c1 = sc1;
        __syncthreads();
        base += 256;
    }

    if (tid == 0) {
        double fast = (double)KNEG * (double)fmaxf(D - S0, 0.f);
        double contrib = 0.0;
        if (c0 >= KNEG) contrib += fast;
        if (c1 >= KNEG) contrib += fast;
        g_part[t]           = contrib;
        g_D[t]              = D;
        g_flags[t]          = (c0 < KNEG);
        g_flags[TLINKS + t] = (c1 < KNEG);
    }
}

// ---------------------------------------------------------------------------
// Fallback + final reduction. 6000 blocks; flagged blocks run the exact
// MSB-first radix select (essentially never). Every block then takes a
// wrap-around ticket; the LAST block does the fixed-order fp64 reduction
// over g_part + g_fb and writes the output.
__global__ void __launch_bounds__(256) fallback_finish_kernel(const float* __restrict__ emb,
                                                              const float* __restrict__ cptr,
                                                              const void*  __restrict__ links,
                                                              float*       __restrict__ out) {
    const int s   = blockIdx.x;
    const int tid = threadIdx.x;

    __shared__ float        q[DIM];
    __shared__ unsigned int hist[256];
    __shared__ unsigned int s_prefix;
    __shared__ int          s_k;
    __shared__ double       ssum[256];
    __shared__ int          scm[256];
    __shared__ int          s_last;

    if (g_flags[s] != 0) {                  // uniform over block — exact path
        const int t    = s % TLINKS;
        const int side = s / TLINKS;        // 0 = left query, 1 = right query

        const float cval = cptr[0];
        const float Kv   = 1.0f / cval;
        const long long node = get_link(links, 2 * t + side, g_is64);

        if (tid < DIM) q[tid] = emb[(size_t)node * DIM + tid];
        if (tid == 0) { s_prefix = 0u; s_k = KNEG; }
        __syncthreads();

        const float D = g_D[t];

        for (int pass = 0; pass < 4; pass++) {
            const int shift = 24 - 8 * pass;
            const unsigned int pmask  = (pass == 0) ? 0u : (0xFFFFFFFFu << (shift + 8));
            const unsigned int prefix = s_prefix;
            hist[tid] = 0u;
            __syncthreads();
            for (int j = tid; j < NNODES; j += 256) {
                float v = sqdist_full(q, emb + (size_t)j * DIM, cval, Kv);
                unsigned int b = __float_as_uint(v);
                if ((b & pmask) == prefix)
                    atomicAdd(&hist[(b >> shift) & 0xFFu], 1u);
            }
            __syncthreads();
            if (tid == 0) {
                int k = s_k;
                unsigned int acc = 0;
                int digit = 0;
                for (; digit < 255; digit++) {
                    if (acc + hist[digit] >= (unsigned)k) break;
                    acc += hist[digit];
                }
                s_k      = k - (int)acc;
                s_prefix = prefix | ((unsigned)digit << shift);
            }
            __syncthreads();
        }

        const unsigned int tau_bits = s_prefix;
        const float        tau      = __uint_as_float(tau_bits);

        int    m_local = 0;
        double sum_local = 0.0;
        for (int j = tid; j < NNODES; j += 256) {
            float v = sqdist_full(q, emb + (size_t)j * DIM, cval, Kv);
            if (__float_as_uint(v) < tau_bits) {
                m_local++;
                sum_local += (double)fmaxf(D - v, 0.f);
            }
        }
        ssum[tid] = sum_local;
        scm[tid]  = m_local;
        __syncthreads();
        for (int o = 128; o > 0; o >>= 1) {
            if (tid < o) { ssum[tid] += ssum[tid + o]; scm[tid] += scm[tid + o]; }
            __syncthreads();
        }
        if (tid == 0) {
            int m = scm[0];
            g_fb[s] = ssum[0] + (double)(KNEG - m) * (double)fmaxf(D - tau, 0.f);
        }
        __syncthreads();
    } else {
        if (tid == 0) g_fb[s] = 0.0;
    }

    // ---- ticket: last block performs the final reduction ----
    if (tid == 0) {
        __threadfence();
        unsigned int old = atomicInc(&g_ticket, 2 * TLINKS - 1);  // wraps to 0
        s_last = (old == 2 * TLINKS - 1);
    }
    __syncthreads();

    if (s_last) {
        __threadfence();
        const volatile double* vp = g_part;
        const volatile double* vf = g_fb;
        double sum = 0.0;
        for (int i = tid; i < TLINKS;     i += 256) sum += vp[i];
        for (int i = tid; i < 2 * TLINKS; i += 256) sum += vf[i];
        ssum[tid] = sum;
        __syncthreads();
        for (int o = 128; o > 0; o >>= 1) {
            if (tid < o) ssum[tid] += ssum[tid + o];
            __syncthreads();
        }
        if (tid == 0)
            out[0] = (float)(ssum[0] / (2.0 * (double)KNEG * (double)TLINKS));
    }
}

// ---------------------------------------------------------------------------
extern "C" void kernel_launch(void* const* d_in, const int* in_sizes, int n_in,
                              void* d_out, int out_size) {
    const float* emb   = nullptr;
    const float* c     = nullptr;
    const void*  links = nullptr;
    for (int i = 0; i < n_in; i++) {
        if (in_sizes[i] == 1)               c     = (const float*)d_in[i];
        else if (in_sizes[i] == 2 * TLINKS) links = d_in[i];
        else                                emb   = (const float*)d_in[i];
    }

    setup_kernel          <<<1, 256>>>((const int*)links);
    hot_kernel            <<<TLINKS, 256>>>(emb, c, links);
    fallback_finish_kernel<<<2 * TLINKS, 256>>>(emb, c, links, (float*)d_out);
}

// round 10
// speedup vs baseline: 1.9277x; 1.0508x over previous
#include <cuda_runtime.h>
#include <math.h>

#define NNODES 30000
#define DIM    128
#define TLINKS 3000
#define KNEG   75
#define GAMMA  1.0f
#define MAXSQ  50.0f
// float(1.0 + 1e-7) == 0x3F800001 (1 ulp above 1.0f) — matches XLA's f32 cast
#define THETA0 (1.0f + 1e-7f)

// ---- device scratch (no allocation allowed) ----
__device__ double       g_part[TLINKS];     // per-link fast-path contribution
__device__ float        g_D[TLINKS];        // per-link D = sqdist(l,r)+GAMMA
__device__ int          g_flags[2*TLINKS];  // per-query fallback flag (0/1)
__device__ double       g_fb[2*TLINKS];     // per-query fallback contribution
__device__ unsigned int g_ticket = 0;       // wraps mod 2*TLINKS each replay

// ---------------------------------------------------------------------------
__device__ __forceinline__ float sqdist_from_mdot(float mdot, float cval, float Kv) {
    float th = fmaxf(-mdot * cval, THETA0);
    float a  = acoshf(th);
    return fminf(Kv * a * a, MAXSQ);
}

// full 128-dim Minkowski sqdist, one thread (fallback path only)
__device__ __forceinline__ float sqdist_full(const float* __restrict__ q,
                                             const float* __restrict__ row,
                                             float cval, float Kv) {
    float md = 0.f;
#pragma unroll
    for (int d = 0; d < DIM; d++) {
        float p = q[d] * row[d];
        md += (d == 0) ? -p : p;
    }
    return sqdist_from_mdot(md, cval, Kv);
}

// ---------------------------------------------------------------------------
// Per-row dot pair with split accumulators (8-deep FFMA chains).
// Returns via s0/s1 the FULL (sub-group-reduced) dots on every lane.
template <bool GUARD>
__device__ __forceinline__ void row_dots(const float* __restrict__ emb, int row,
                                         const float4* a0, const float4* a1, int sub,
                                         float& s0, float& s1) {
    float s0a = 0.f, s0b = 0.f, s1a = 0.f, s1b = 0.f;
    if (!GUARD || row < NNODES) {
        const float4* p = (const float4*)(emb + (size_t)row * DIM);
        float4 y0 = p[0 * 8 + sub];
        float4 y1 = p[1 * 8 + sub];
        float4 y2 = p[2 * 8 + sub];
        float4 y3 = p[3 * 8 + sub];
        s0a = a0[0].x*y0.x + a0[0].y*y0.y + a0[0].z*y0.z + a0[0].w*y0.w
            + a0[1].x*y1.x + a0[1].y*y1.y + a0[1].z*y1.z + a0[1].w*y1.w;
        s0b = a0[2].x*y2.x + a0[2].y*y2.y + a0[2].z*y2.z + a0[2].w*y2.w
            + a0[3].x*y3.x + a0[3].y*y3.y + a0[3].z*y3.z + a0[3].w*y3.w;
        s1a = a1[0].x*y0.x + a1[0].y*y0.y + a1[0].z*y0.z + a1[0].w*y0.w
            + a1[1].x*y1.x + a1[1].y*y1.y + a1[1].z*y1.z + a1[1].w*y1.w;
        s1b = a1[2].x*y2.x + a1[2].y*y2.y + a1[2].z*y2.z + a1[2].w*y2.w
            + a1[3].x*y3.x + a1[3].y*y3.y + a1[3].z*y3.z + a1[3].w*y3.w;
    } else {
        s0a = -1e30f; s1a = -1e30f;    // guarded-out rows never count
    }
    s0 = s0a + s0b;
    s1 = s1a + s1b;
    s0 += __shfl_xor_sync(0xffffffffu, s0, 1);
    s1 += __shfl_xor_sync(0xffffffffu, s1, 1);
    s0 += __shfl_xor_sync(0xffffffffu, s0, 2);
    s1 += __shfl_xor_sync(0xffffffffu, s1, 2);
    s0 += __shfl_xor_sync(0xffffffffu, s0, 4);
    s1 += __shfl_xor_sync(0xffffffffu, s1, 4);
}

// ---------------------------------------------------------------------------
// HOT kernel: one block (256 threads) per link; 4 blocks/SM.
//  - is64 detected per-warp (warps 0/1) by a 32-sample ballot over odd int32
//    words: int64 links < 30000 have ALL odd words zero; for int32 links the
//    odd words are right-node ids (P(32 consecutive all zero) ~ 30000^-32).
//  - coalesced candidate reads: lane sub owns float4s j = i*8+sub, so each
//    8-lane sub-group covers one contiguous 128-B line per i.
//  - count rows with theta clipped (mdot >= -THETA0/c <=> sqdist == S0);
//    count >= 75  =>  top-75 all exactly S0  =>  75 * relu(D - S0).
__global__ void __launch_bounds__(256, 4) hot_kernel(const float* __restrict__ emb,
                                                     const float* __restrict__ cptr,
                                                     const void*  __restrict__ links) {
    __shared__ float q[2][DIM];
    __shared__ float sD;
    __shared__ int   sc0, sc1;

    const int t    = blockIdx.x;
    const int tid  = threadIdx.x;
    const int w    = tid >> 5;
    const int lane = tid & 31;
    const int sub  = lane & 7;          // 8-lane sub-group position

    const float cval = cptr[0];
    const float Kv   = 1.0f / cval;

    // warps 0/1: detect dtype, fetch own node, stage its q row (float4)
    if (w < 2) {
        const int* links32 = (const int*)links;
        int idx = t + lane; if (idx >= TLINKS) idx -= TLINKS;
        unsigned nz = __ballot_sync(0xffffffffu, links32[2 * idx + 1] != 0);
        const int is64 = (nz == 0);
        long long node = is64 ? ((const long long*)links)[2 * t + w]
                              : (long long)links32[2 * t + w];
        ((float4*)q[w])[lane] = ((const float4*)(emb + (size_t)node * DIM))[lane];
    }
    if (tid == 0) { sc0 = 0; sc1 = 0; }
    __syncthreads();

    // per-lane register slices, mapping j = i*8 + sub (dim 0 is i=0,sub=0,.x)
    float4 a0[4], a1[4];
#pragma unroll
    for (int i = 0; i < 4; i++) {
        a0[i] = ((const float4*)q[0])[i * 8 + sub];
        a1[i] = ((const float4*)q[1])[i * 8 + sub];
    }
    if (sub == 0) { a0[0].x = -a0[0].x; a1[0].x = -a1[0].x; }

    // D = sqdist(left,right) + GAMMA  (sign-folded a0 vs RAW q1)
    if (w == 0) {
        float s = 0.f;
#pragma unroll
        for (int i = 0; i < 4; i++) {
            float4 b = ((const float4*)q[1])[i * 8 + sub];
            s += a0[i].x * b.x + a0[i].y * b.y + a0[i].z * b.z + a0[i].w * b.w;
        }
        s += __shfl_xor_sync(0xffffffffu, s, 1);
        s += __shfl_xor_sync(0xffffffffu, s, 2);
        s += __shfl_xor_sync(0xffffffffu, s, 4);
        if (tid == 0) sD = sqdist_from_mdot(s, cval, Kv) + GAMMA;
    }
    __syncthreads();
    const float D = sD;

    float acz = acoshf(THETA0);
    const float S0  = fminf(Kv * acz * acz, MAXSQ);
    const float thr = -(THETA0 * Kv);    // mdot >= thr  <=>  theta clips to 1+EPS

    const int rbase0 = (w << 5) + (lane >> 3);
    int l0 = 0, l1 = 0;

    // ---- chunk 0: rows 0..255, no bounds guard (256 << NNODES) ----
#pragma unroll 4
    for (int g = 0; g < 8; g++) {
        float s0, s1;
        row_dots<false>(emb, rbase0 + g * 4, a0, a1, sub, s0, s1);
        l0 += (s0 >= thr);
        l1 += (s1 >= thr);
    }
    // lanes 0-7 hold subgroup0's count, 8-15 subgroup1's, ...:
    // xor8 + xor16 -> exact warp count on every lane.
    l0 += __shfl_xor_sync(0xffffffffu, l0, 8);
    l1 += __shfl_xor_sync(0xffffffffu, l1, 8);
    l0 += __shfl_xor_sync(0xffffffffu, l0, 16);
    l1 += __shfl_xor_sync(0xffffffffu, l1, 16);
    if (lane == 0) { atomicAdd(&sc0, l0); atomicAdd(&sc1, l1); }
    __syncthreads();
    int c0 = sc0, c1 = sc1;
    __syncthreads();

    // ---- rare continuation: more chunks until both counts reach 75 ----
    int base = 256;
    while (base < NNODES && (c0 < KNEG || c1 < KNEG)) {
        int m0 = 0, m1 = 0;
#pragma unroll 2
        for (int g = 0; g < 8; g++) {
            float s0, s1;
            row_dots<true>(emb, base + rbase0 + g * 4, a0, a1, sub, s0, s1);
            m0 += (s0 >= thr);
            m1 += (s1 >= thr);
        }
        m0 += __shfl_xor_sync(0xffffffffu, m0, 8);
        m1 += __shfl_xor_sync(0xffffffffu, m1, 8);
        m0 += __shfl_xor_sync(0xffffffffu, m0, 16);
        m1 += __shfl_xor_sync(0xffffffffu, m1, 16);
        if (lane == 0) { atomicAdd(&sc0, m0); atomicAdd(&sc1, m1); }
        __syncthreads();
        c0 = sc0; c1 = sc1;
        __syncthreads();
        base += 256;
    }

    if (tid == 0) {
        double fast = (double)KNEG * (double)fmaxf(D - S0, 0.f);
        double contrib = 0.0;
        if (c0 >= KNEG) contrib += fast;
        if (c1 >= KNEG) contrib += fast;
        g_part[t]           = contrib;
        g_D[t]              = D;
        g_flags[t]          = (c0 < KNEG);
        g_flags[TLINKS + t] = (c1 < KNEG);
    }
}

// ---------------------------------------------------------------------------
// Fallback + final reduction. 6000 blocks; flagged blocks run the exact
// MSB-first radix select (essentially never). Every block then takes a
// wrap-around ticket; the LAST block does the fixed-order fp64 reduction
// over g_part + g_fb and writes the output.
__global__ void __launch_bounds__(256) fallback_finish_kernel(const float* __restrict__ emb,
                                                              const float* __restrict__ cptr,
                                                              const void*  __restrict__ links,
                                                              float*       __restrict__ out) {
    const int s   = blockIdx.x;
    const int tid = threadIdx.x;

    __shared__ float        q[DIM];
    __shared__ unsigned int hist[256];
    __shared__ unsigned int s_prefix;
    __shared__ int          s_k;
    __shared__ double       ssum[256];
    __shared__ int          scm[256];
    __shared__ int          s_last;

    if (g_flags[s] != 0) {                  // uniform over block — exact path
        const int t    = s % TLINKS;
        const int side = s / TLINKS;        // 0 = left query, 1 = right query

        const float cval = cptr[0];
        const float Kv   = 1.0f / cval;
        const int* links32 = (const int*)links;

        // dtype detection (32 odd-word samples, block-wide OR)
        int mybad = 0;
        if (tid < 32) {
            int idx = t + tid; if (idx >= TLINKS) idx -= TLINKS;
            mybad = (links32[2 * idx + 1] != 0);
        }
        const int is64 = __syncthreads_or(mybad) ? 0 : 1;

        const long long node = is64 ? ((const long long*)links)[2 * t + side]
                                    : (long long)links32[2 * t + side];

        if (tid < DIM) q[tid] = emb[(size_t)node * DIM + tid];
        if (tid == 0) { s_prefix = 0u; s_k = KNEG; }
        __syncthreads();

        const float D = g_D[t];

        for (int pass = 0; pass < 4; pass++) {
            const int shift = 24 - 8 * pass;
            const unsigned int pmask  = (pass == 0) ? 0u : (0xFFFFFFFFu << (shift + 8));
            const unsigned int prefix = s_prefix;
            hist[tid] = 0u;
            __syncthreads();
            for (int j = tid; j < NNODES; j += 256) {
                float v = sqdist_full(q, emb + (size_t)j * DIM, cval, Kv);
                unsigned int b = __float_as_uint(v);
                if ((b & pmask) == prefix)
                    atomicAdd(&hist[(b >> shift) & 0xFFu], 1u);
            }
            __syncthreads();
            if (tid == 0) {
                int k = s_k;
                unsigned int acc = 0;
                int digit = 0;
                for (; digit < 255; digit++) {
                    if (acc + hist[digit] >= (unsigned)k) break;
                    acc += hist[digit];
                }
                s_k      = k - (int)acc;
                s_prefix = prefix | ((unsigned)digit << shift);
            }
            __syncthreads();
        }

        const unsigned int tau_bits = s_prefix;
        const float        tau      = __uint_as_float(tau_bits);

        int    m_local = 0;
        double sum_local = 0.0;
        for (int j = tid; j < NNODES; j += 256) {
            float v = sqdist_full(q, emb + (size_t)j * DIM, cval, Kv);
            if (__float_as_uint(v) < tau_bits) {
                m_local++;
                sum_local += (double)fmaxf(D - v, 0.f);
            }
        }
        ssum[tid] = sum_local;
        scm[tid]  = m_local;
        __syncthreads();
        for (int o = 128; o > 0; o >>= 1) {
            if (tid < o) { ssum[tid] += ssum[tid + o]; scm[tid] += scm[tid + o]; }
            __syncthreads();
        }
        if (tid == 0) {
            int m = scm[0];
            g_fb[s] = ssum[0] + (double)(KNEG - m) * (double)fmaxf(D - tau, 0.f);
        }
        __syncthreads();
    } else {
        if (tid == 0) g_fb[s] = 0.0;
    }

    // ---- ticket: last block performs the final reduction ----
    if (tid == 0) {
        __threadfence();
        unsigned int old = atomicInc(&g_ticket, 2 * TLINKS - 1);  // wraps to 0
        s_last = (old == 2 * TLINKS - 1);
    }
    __syncthreads();

    if (s_last) {
        __threadfence();
        const volatile double* vp = g_part;
        const volatile double* vf = g_fb;
        double sum = 0.0;
        for (int i = tid; i < TLINKS;     i += 256) sum += vp[i];
        for (int i = tid; i < 2 * TLINKS; i += 256) sum += vf[i];
        ssum[tid] = sum;
        __syncthreads();
        for (int o = 128; o > 0; o >>= 1) {
            if (tid < o) ssum[tid] += ssum[tid + o];
            __syncthreads();
        }
        if (tid == 0)
            out[0] = (float)(ssum[0] / (2.0 * (double)KNEG * (double)TLINKS));
    }
}

// ---------------------------------------------------------------------------
extern "C" void kernel_launch(void* const* d_in, const int* in_sizes, int n_in,
                              void* d_out, int out_size) {
    const float* emb   = nullptr;
    const float* c     = nullptr;
    const void*  links = nullptr;
    for (int i = 0; i < n_in; i++) {
        if (in_sizes[i] == 1)               c     = (const float*)d_in[i];
        else if (in_sizes[i] == 2 * TLINKS) links = d_in[i];
        else                                emb   = (const float*)d_in[i];
    }

    hot_kernel            <<<TLINKS, 256>>>(emb, c, links);
    fallback_finish_kernel<<<2 * TLINKS, 256>>>(emb, c, links, (float*)d_out);
}

// round 11
// speedup vs baseline: 4.4837x; 2.3260x over previous
#include <cuda_runtime.h>
#include <math.h>

#define NNODES 30000
#define DIM    128
#define TLINKS 3000
#define KNEG   75
#define GAMMA  1.0f
#define MAXSQ  50.0f
// float(1.0 + 1e-7) == 0x3F800001 (1 ulp above 1.0f) — matches XLA's f32 cast
#define THETA0 (1.0f + 1e-7f)
#define FBGRID 128

// ---- device scratch (no allocation allowed) ----
__device__ double       g_part[TLINKS];    // per-link fast-path contribution
__device__ float        g_D[TLINKS];       // per-link D = sqdist(l,r)+GAMMA
__device__ int          g_queue[2*TLINKS]; // flagged query ids (side*TLINKS+t)
__device__ int          g_nfb   = 0;       // queue length; reset by finisher
__device__ double       g_fbsum = 0.0;     // fallback sum;  reset by finisher
__device__ unsigned int g_ticket = 0;      // wraps mod FBGRID each replay

// ---------------------------------------------------------------------------
__device__ __forceinline__ float sqdist_from_mdot(float mdot, float cval, float Kv) {
    float th = fmaxf(-mdot * cval, THETA0);
    float a  = acoshf(th);
    return fminf(Kv * a * a, MAXSQ);
}

// full 128-dim Minkowski sqdist, one thread (fallback path only)
__device__ __forceinline__ float sqdist_full(const float* __restrict__ q,
                                             const float* __restrict__ row,
                                             float cval, float Kv) {
    float md = 0.f;
#pragma unroll
    for (int d = 0; d < DIM; d++) {
        float p = q[d] * row[d];
        md += (d == 0) ? -p : p;
    }
    return sqdist_from_mdot(md, cval, Kv);
}

// ---------------------------------------------------------------------------
// Per-row dot pair with split accumulators (8-deep FFMA chains).
// Returns via s0/s1 the FULL (sub-group-reduced) dots on every lane.
template <bool GUARD>
__device__ __forceinline__ void row_dots(const float* __restrict__ emb, int row,
                                         const float4* a0, const float4* a1, int sub,
                                         float& s0, float& s1) {
    float s0a = 0.f, s0b = 0.f, s1a = 0.f, s1b = 0.f;
    if (!GUARD || row < NNODES) {
        const float4* p = (const float4*)(emb + (size_t)row * DIM);
        float4 y0 = p[0 * 8 + sub];
        float4 y1 = p[1 * 8 + sub];
        float4 y2 = p[2 * 8 + sub];
        float4 y3 = p[3 * 8 + sub];
        s0a = a0[0].x*y0.x + a0[0].y*y0.y + a0[0].z*y0.z + a0[0].w*y0.w
            + a0[1].x*y1.x + a0[1].y*y1.y + a0[1].z*y1.z + a0[1].w*y1.w;
        s0b = a0[2].x*y2.x + a0[2].y*y2.y + a0[2].z*y2.z + a0[2].w*y2.w
            + a0[3].x*y3.x + a0[3].y*y3.y + a0[3].z*y3.z + a0[3].w*y3.w;
        s1a = a1[0].x*y0.x + a1[0].y*y0.y + a1[0].z*y0.z + a1[0].w*y0.w
            + a1[1].x*y1.x + a1[1].y*y1.y + a1[1].z*y1.z + a1[1].w*y1.w;
        s1b = a1[2].x*y2.x + a1[2].y*y2.y + a1[2].z*y2.z + a1[2].w*y2.w
            + a1[3].x*y3.x + a1[3].y*y3.y + a1[3].z*y3.z + a1[3].w*y3.w;
    } else {
        s0a = -1e30f; s1a = -1e30f;    // guarded-out rows never count
    }
    s0 = s0a + s0b;
    s1 = s1a + s1b;
    s0 += __shfl_xor_sync(0xffffffffu, s0, 1);
    s1 += __shfl_xor_sync(0xffffffffu, s1, 1);
    s0 += __shfl_xor_sync(0xffffffffu, s0, 2);
    s1 += __shfl_xor_sync(0xffffffffu, s1, 2);
    s0 += __shfl_xor_sync(0xffffffffu, s0, 4);
    s1 += __shfl_xor_sync(0xffffffffu, s1, 4);
}

// ---------------------------------------------------------------------------
// HOT kernel: one block (256 threads) per link; 4 blocks/SM.
//  - is64 detected per-warp (warps 0/1) by a 32-sample ballot over odd int32
//    words (int64 ids < 30000 have all odd words zero).
//  - coalesced candidate reads: lane sub owns float4s j = i*8+sub.
//  - count rows with theta clipped (mdot >= -THETA0/c <=> sqdist == S0);
//    count >= 75  =>  top-75 all exactly S0  =>  75 * relu(D - S0).
//    Else (never in practice): push query onto the fallback work-queue.
__global__ void __launch_bounds__(256, 4) hot_kernel(const float* __restrict__ emb,
                                                     const float* __restrict__ cptr,
                                                     const void*  __restrict__ links) {
    __shared__ float q[2][DIM];
    __shared__ float sD;
    __shared__ int   sc0, sc1;

    const int t    = blockIdx.x;
    const int tid  = threadIdx.x;
    const int w    = tid >> 5;
    const int lane = tid & 31;
    const int sub  = lane & 7;          // 8-lane sub-group position

    const float cval = cptr[0];
    const float Kv   = 1.0f / cval;

    // warps 0/1: detect dtype, fetch own node, stage its q row (float4)
    if (w < 2) {
        const int* links32 = (const int*)links;
        int idx = t + lane; if (idx >= TLINKS) idx -= TLINKS;
        unsigned nz = __ballot_sync(0xffffffffu, links32[2 * idx + 1] != 0);
        const int is64 = (nz == 0);
        long long node = is64 ? ((const long long*)links)[2 * t + w]
                              : (long long)links32[2 * t + w];
        ((float4*)q[w])[lane] = ((const float4*)(emb + (size_t)node * DIM))[lane];
    }
    if (tid == 0) { sc0 = 0; sc1 = 0; }
    __syncthreads();

    // per-lane register slices, mapping j = i*8 + sub (dim 0 is i=0,sub=0,.x)
    float4 a0[4], a1[4];
#pragma unroll
    for (int i = 0; i < 4; i++) {
        a0[i] = ((const float4*)q[0])[i * 8 + sub];
        a1[i] = ((const float4*)q[1])[i * 8 + sub];
    }
    if (sub == 0) { a0[0].x = -a0[0].x; a1[0].x = -a1[0].x; }

    // D = sqdist(left,right) + GAMMA  (sign-folded a0 vs RAW q1)
    if (w == 0) {
        float s = 0.f;
#pragma unroll
        for (int i = 0; i < 4; i++) {
            float4 b = ((const float4*)q[1])[i * 8 + sub];
            s += a0[i].x * b.x + a0[i].y * b.y + a0[i].z * b.z + a0[i].w * b.w;
        }
        s += __shfl_xor_sync(0xffffffffu, s, 1);
        s += __shfl_xor_sync(0xffffffffu, s, 2);
        s += __shfl_xor_sync(0xffffffffu, s, 4);
        if (tid == 0) sD = sqdist_from_mdot(s, cval, Kv) + GAMMA;
    }
    __syncthreads();
    const float D = sD;

    float acz = acoshf(THETA0);
    const float S0  = fminf(Kv * acz * acz, MAXSQ);
    const float thr = -(THETA0 * Kv);    // mdot >= thr  <=>  theta clips to 1+EPS

    const int rbase0 = (w << 5) + (lane >> 3);
    int l0 = 0, l1 = 0;

    // ---- chunk 0: rows 0..255, no bounds guard (256 << NNODES) ----
#pragma unroll 4
    for (int g = 0; g < 8; g++) {
        float s0, s1;
        row_dots<false>(emb, rbase0 + g * 4, a0, a1, sub, s0, s1);
        l0 += (s0 >= thr);
        l1 += (s1 >= thr);
    }
    // xor8 + xor16 -> exact warp count on every lane.
    l0 += __shfl_xor_sync(0xffffffffu, l0, 8);
    l1 += __shfl_xor_sync(0xffffffffu, l1, 8);
    l0 += __shfl_xor_sync(0xffffffffu, l0, 16);
    l1 += __shfl_xor_sync(0xffffffffu, l1, 16);
    if (lane == 0) { atomicAdd(&sc0, l0); atomicAdd(&sc1, l1); }
    __syncthreads();
    int c0 = sc0, c1 = sc1;
    __syncthreads();

    // ---- rare continuation: more chunks until both counts reach 75 ----
    int base = 256;
    while (base < NNODES && (c0 < KNEG || c1 < KNEG)) {
        int m0 = 0, m1 = 0;
#pragma unroll 2
        for (int g = 0; g < 8; g++) {
            float s0, s1;
            row_dots<true>(emb, base + rbase0 + g * 4, a0, a1, sub, s0, s1);
            m0 += (s0 >= thr);
            m1 += (s1 >= thr);
        }
        m0 += __shfl_xor_sync(0xffffffffu, m0, 8);
        m1 += __shfl_xor_sync(0xffffffffu, m1, 8);
        m0 += __shfl_xor_sync(0xffffffffu, m0, 16);
        m1 += __shfl_xor_sync(0xffffffffu, m1, 16);
        if (lane == 0) { atomicAdd(&sc0, m0); atomicAdd(&sc1, m1); }
        __syncthreads();
        c0 = sc0; c1 = sc1;
        __syncthreads();
        base += 256;
    }

    if (tid == 0) {
        double fast = (double)KNEG * (double)fmaxf(D - S0, 0.f);
        double contrib = 0.0;
        if (c0 >= KNEG) contrib += fast;
        if (c1 >= KNEG) contrib += fast;
        g_part[t] = contrib;
        g_D[t]    = D;
        if (c0 < KNEG) g_queue[atomicAdd(&g_nfb, 1)] = t;            // side 0
        if (c1 < KNEG) g_queue[atomicAdd(&g_nfb, 1)] = TLINKS + t;   // side 1
    }
}

// ---------------------------------------------------------------------------
// Fallback + final reduction. FBGRID blocks, ONE wave. Each block strides
// over the (normally empty) work queue; flagged queries get the exact
// MSB-first radix select of the 75th-smallest sqdist. Last-ticket block
// reduces g_part + g_fbsum, writes out, and resets queue state for the
// next graph replay.
__global__ void __launch_bounds__(256) fallback_finish_kernel(const float* __restrict__ emb,
                                                              const float* __restrict__ cptr,
                                                              const void*  __restrict__ links,
                                                              float*       __restrict__ out) {
    const int tid = threadIdx.x;

    __shared__ float        q[DIM];
    __shared__ unsigned int hist[256];
    __shared__ unsigned int s_prefix;
    __shared__ int          s_k;
    __shared__ double       ssum[256];
    __shared__ int          scm[256];
    __shared__ int          s_last;

    const int nfb = g_nfb;   // written by hot_kernel (kernel-boundary visible)

    for (int qi = blockIdx.x; qi < nfb; qi += FBGRID) {
        const int s    = g_queue[qi];
        const int t    = s % TLINKS;
        const int side = s / TLINKS;

        const float cval = cptr[0];
        const float Kv   = 1.0f / cval;
        const int* links32 = (const int*)links;

        // dtype detection (32 odd-word samples, block-wide OR)
        int mybad = 0;
        if (tid < 32) {
            int idx = t + tid; if (idx >= TLINKS) idx -= TLINKS;
            mybad = (links32[2 * idx + 1] != 0);
        }
        const int is64 = __syncthreads_or(mybad) ? 0 : 1;

        const long long node = is64 ? ((const long long*)links)[2 * t + side]
                                    : (long long)links32[2 * t + side];

        if (tid < DIM) q[tid] = emb[(size_t)node * DIM + tid];
        if (tid == 0) { s_prefix = 0u; s_k = KNEG; }
        __syncthreads();

        const float D = g_D[t];

        for (int pass = 0; pass < 4; pass++) {
            const int shift = 24 - 8 * pass;
            const unsigned int pmask  = (pass == 0) ? 0u : (0xFFFFFFFFu << (shift + 8));
            const unsigned int prefix = s_prefix;
            hist[tid] = 0u;
            __syncthreads();
            for (int j = tid; j < NNODES; j += 256) {
                float v = sqdist_full(q, emb + (size_t)j * DIM, cval, Kv);
                unsigned int b = __float_as_uint(v);
                if ((b & pmask) == prefix)
                    atomicAdd(&hist[(b >> shift) & 0xFFu], 1u);
            }
            __syncthreads();
            if (tid == 0) {
                int k = s_k;
                unsigned int acc = 0;
                int digit = 0;
                for (; digit < 255; digit++) {
                    if (acc + hist[digit] >= (unsigned)k) break;
                    acc += hist[digit];
                }
                s_k      = k - (int)acc;
                s_prefix = prefix | ((unsigned)digit << shift);
            }
            __syncthreads();
        }

        const unsigned int tau_bits = s_prefix;
        const float        tau      = __uint_as_float(tau_bits);

        int    m_local = 0;
        double sum_local = 0.0;
        for (int j = tid; j < NNODES; j += 256) {
            float v = sqdist_full(q, emb + (size_t)j * DIM, cval, Kv);
            if (__float_as_uint(v) < tau_bits) {
                m_local++;
                sum_local += (double)fmaxf(D - v, 0.f);
            }
        }
        ssum[tid] = sum_local;
        scm[tid]  = m_local;
        __syncthreads();
        for (int o = 128; o > 0; o >>= 1) {
            if (tid < o) { ssum[tid] += ssum[tid + o]; scm[tid] += scm[tid + o]; }
            __syncthreads();
        }
        if (tid == 0) {
            int m = scm[0];
            double res = ssum[0] + (double)(KNEG - m) * (double)fmaxf(D - tau, 0.f);
            atomicAdd(&g_fbsum, res);
        }
        __syncthreads();
    }

    // ---- ticket: last block performs the final reduction + state reset ----
    if (tid == 0) {
        __threadfence();
        unsigned int old = atomicInc(&g_ticket, FBGRID - 1);  // wraps to 0
        s_last = (old == FBGRID - 1);
    }
    __syncthreads();

    if (s_last) {
        __threadfence();
        const volatile double* vp = g_part;
        double sum = 0.0;
        for (int i = tid; i < TLINKS; i += 256) sum += vp[i];
        ssum[tid] = sum;
        __syncthreads();
        for (int o = 128; o > 0; o >>= 1) {
            if (tid < o) ssum[tid] += ssum[tid + o];
            __syncthreads();
        }
        if (tid == 0) {
            double total = ssum[0] + g_fbsum;
            out[0] = (float)(total / (2.0 * (double)KNEG * (double)TLINKS));
            g_nfb   = 0;      // reset queue state for the next graph replay
            g_fbsum = 0.0;
        }
    }
}

// ---------------------------------------------------------------------------
extern "C" void kernel_launch(void* const* d_in, const int* in_sizes, int n_in,
                              void* d_out, int out_size) {
    const float* emb   = nullptr;
    const float* c     = nullptr;
    const void*  links = nullptr;
    for (int i = 0; i < n_in; i++) {
        if (in_sizes[i] == 1)               c     = (const float*)d_in[i];
        else if (in_sizes[i] == 2 * TLINKS) links = d_in[i];
        else                                emb   = (const float*)d_in[i];
    }

    hot_kernel            <<<TLINKS, 256>>>(emb, c, links);
    fallback_finish_kernel<<<FBGRID, 256>>>(emb, c, links, (float*)d_out);
}